// round 7
// baseline (speedup 1.0000x reference)
#include <cuda_runtime.h>

// BezierToImageLayer — sparse Gaussian splat, round 7.
// R7 vs R6 (68.4us, issue stuck at 65%):
//  - NO per-sample SHFL broadcast: per-curve power-basis conversion (uniform),
//    then X,Y per sample via Horner with COMPILE-TIME t_s immediates (full
//    30-unroll -> constant-folded FFMA-imm, rt=1). Removes the 26-cyc SHFL
//    latency from every sample's dependency chain and halves MIO ops/sample.
//  - min(mi,59) guard vs rounding overflow at the top edge.
//  - everything else unchanged from R6 (best-of assembly).

#define BDIM     128
#define NWARPS   4
#define NSPLIT   4
#define WPIX     60
#define AROWS    67                         // rows -3..63
#define STRIDE   68                         // 68/2=34 ≡ 2 (mod 16): conflict-free LDS.64
#define RPAD     3
#define CPAD     4
#define NSAMP    30
#define NCURVE   160
#define CPT      (NCURVE / NSPLIT)          // 40 curves per task
#define CPW      (CPT / NWARPS)             // 10 curves per warp
#define COPY_W   (AROWS * STRIDE)           // 4556 floats
#define ACC_WORDS (NWARPS * COPY_W)         // 18224 floats = 72896 B

#define NBATCH   256
#define IMG      (WPIX * WPIX)

__device__ float g_scratch[NBATCH * NSPLIT * IMG];   // 14.7 MB partials (L2-hot)
__device__ int   g_cnt[NBATCH];                      // zero-init; reset by last CTA

__device__ __forceinline__ float ex2f(float a) {
    float r; asm("ex2.approx.f32 %0, %1;" : "=f"(r) : "f"(a)); return r;
}

__global__ __launch_bounds__(BDIM, 3)
void bezier_splat_kernel(const float* __restrict__ x, float* __restrict__ out)
{
    extern __shared__ float acc[];   // [NWARPS][AROWS][STRIDE], per-warp private

    const int task = blockIdx.x;          // 0..1023
    const int b    = task >> 2;
    const int part = task & (NSPLIT - 1);
    const int tid  = threadIdx.x;
    const int w    = tid >> 5;
    const int lane = tid & 31;

    // ---- zero private accumulators ----
    float4* az = (float4*)acc;
    for (int i = tid; i < ACC_WORDS / 4; i += BDIM)
        az[i] = make_float4(0.f, 0.f, 0.f, 0.f);
    __syncthreads();

    float* __restrict__ my = acc + w * COPY_W + RPAD * STRIDE + CPAD;

    const int ra3 = (lane >> 2) + 3;   // row residue (mod 8), pre-biased
    const int pc  = lane & 3;          // column-pair residue (mod 4)

    const float C2 = -2.0037431123457827f;   // -(5000/3600)*log2(e)

    const float* __restrict__ xb = x + ((size_t)b * NCURVE + part * CPT) * 8;

    for (int c = 0; c < CPW; ++c) {
        const float* ct = xb + (w + NWARPS * c) * 8;

        // control points in pixel units (uniform across lanes)
        const float p0x = 60.0f * ct[0], p0y = 60.0f * ct[1];
        const float p1x = 60.0f * ct[2], p1y = 60.0f * ct[3];
        const float p2x = 60.0f * ct[4], p2y = 60.0f * ct[5];
        const float p3x = 60.0f * ct[6], p3y = 60.0f * ct[7];

        // power basis: X(t) = ((c3*t + c2)*t + c1)*t + c0
        // (reference basis == standard Bezier with reversed ctrl order)
        const float c0x = p3x;
        const float c1x = 3.0f * (p2x - p3x);
        const float c2x = 3.0f * (p1x - 2.0f * p2x + p3x);
        const float c3x = (p0x - p3x) + 3.0f * (p2x - p1x);
        const float c0y = p3y;
        const float c1y = 3.0f * (p2y - p3y);
        const float c2y = 3.0f * (p1y - 2.0f * p2y + p3y);
        const float c3y = (p0y - p3y) + 3.0f * (p2y - p1y);

        #pragma unroll
        for (int s = 0; s < NSAMP; ++s) {
            // t_s folds to a literal after full unroll -> FFMA-imm Horner
            const float uu = (float)s * (1.0f / 30.0f);
            const float tt = 2.0f*uu*uu*uu - 3.0f*uu*uu + 2.0f*uu;

            const float Xp = fmaf(fmaf(fmaf(c3x, tt, c2x), tt, c1x), tt, c0x);
            const float Yp = fmaf(fmaf(fmaf(c3y, tt, c2y), tt, c1y), tt, c0y);

            int mi = (int)Xp;  mi = min(mi, WPIX - 1);   // [0,59]
            int mj = (int)Yp;  mj = min(mj, WPIX - 1);

            // row: i in [mi-3, mi+4], i ≡ ra (mod 8)
            const int i  = mi - 3 + ((ra3 - mi) & 7);
            // col-pairs: P in [P0, P0+3], P ≡ pc (mod 4); cols 2P, 2P+1
            const int P0 = (mj - 3) >> 1;
            const int P  = P0 + ((pc - P0) & 3);

            const float dx  = (float)i       - Xp;
            const float dy1 = (float)(2 * P) - Yp;

            const float sq = fmaf(dy1, dy1, dx * dx);
            const float e1 = sq * C2;
            const float td = fmaf(dy1, 2.0f * C2, C2);   // C2*(dy1+1)^2 - C2*dy1^2
            const float g1 = ex2f(e1);
            const float g2 = ex2f(e1 + td);

            float2* __restrict__ p = (float2*)(my + i * STRIDE + 2 * P);
            float2 v = *p;
            v.x += g1;
            v.y += g2;
            *p = v;
        }
    }
    __syncthreads();

    // ---- reduce 4 private copies -> scratch partial (float4) ----
    float4* __restrict__ sp4 = (float4*)(g_scratch + (size_t)task * IMG);
    const float* __restrict__ a0 = acc + RPAD * STRIDE + CPAD;
    for (int q = tid; q < IMG / 4; q += BDIM) {          // 900 quads
        const int i = q / (WPIX / 4);
        const int k = q - i * (WPIX / 4);
        const int o = i * STRIDE + 4 * k;
        float4 s0 = *(const float4*)(a0 + o);
        #pragma unroll
        for (int ww = 1; ww < NWARPS; ++ww) {
            const float4 v = *(const float4*)(a0 + ww * COPY_W + o);
            s0.x += v.x; s0.y += v.y; s0.z += v.z; s0.w += v.w;
        }
        sp4[q] = s0;
    }

    // ---- last task of this batch combines the 4 partials ----
    __threadfence();
    __syncthreads();
    __shared__ int s_last;
    if (tid == 0) {
        int old = atomicAdd(&g_cnt[b], 1);
        s_last = (old == NSPLIT - 1);
    }
    __syncthreads();
    if (s_last) {
        __threadfence();   // acquire: see all tasks' scratch writes
        const float4* __restrict__ base =
            (const float4*)(g_scratch + (size_t)b * NSPLIT * IMG);
        float4* __restrict__ ob = (float4*)(out + (size_t)b * IMG);
        for (int q = tid; q < IMG / 4; q += BDIM) {
            float4 s0 = base[q];
            #pragma unroll
            for (int k = 1; k < NSPLIT; ++k) {
                const float4 v = base[k * (IMG / 4) + q];
                s0.x += v.x; s0.y += v.y; s0.z += v.z; s0.w += v.w;
            }
            s0.x = fminf(s0.x, 1.0f);
            s0.y = fminf(s0.y, 1.0f);
            s0.z = fminf(s0.z, 1.0f);
            s0.w = fminf(s0.w, 1.0f);
            ob[q] = s0;
        }
        if (tid == 0) g_cnt[b] = 0;   // reset for next graph replay
    }
}

extern "C" void kernel_launch(void* const* d_in, const int* in_sizes, int n_in,
                              void* d_out, int out_size)
{
    (void)in_sizes; (void)n_in; (void)out_size;
    const float* x = (const float*)d_in[0];
    float* out     = (float*)d_out;

    cudaFuncSetAttribute(bezier_splat_kernel,
                         cudaFuncAttributeMaxDynamicSharedMemorySize,
                         ACC_WORDS * (int)sizeof(float));

    bezier_splat_kernel<<<NBATCH * NSPLIT, BDIM, ACC_WORDS * (int)sizeof(float)>>>(x, out);
}

// round 8
// speedup vs baseline: 1.0579x; 1.0579x over previous
#include <cuda_runtime.h>

// BezierToImageLayer — sparse Gaussian splat, round 8.
// R8 vs R6 (68.4us, issue 65.3% == 3x single-warp-serial model):
//  - EXPLICIT 2-deep software pipeline in the sample loop: compute sample s's
//    (addr,g1,g2), then perform sample (s-1)'s LDS/FADD/STS RMW. The 29-cyc LDS
//    wait is covered by the next sample's compute instead of stalling the warp.
//  - e1 via negated-operand FFMA (1 instr saved/sample).
//  - everything else identical to R6.

#define BDIM     128
#define NWARPS   4
#define NSPLIT   4
#define WPIX     60
#define AROWS    67                         // rows -3..63
#define STRIDE   68                         // 68/2=34 ≡ 2 (mod 16): conflict-free LDS.64
#define RPAD     3
#define CPAD     4
#define NSAMP    30
#define NCURVE   160
#define CPT      (NCURVE / NSPLIT)          // 40 curves per task
#define CPW      (CPT / NWARPS)             // 10 curves per warp
#define COPY_W   (AROWS * STRIDE)           // 4556 floats
#define ACC_WORDS (NWARPS * COPY_W)         // 18224 floats = 72896 B

#define NBATCH   256
#define IMG      (WPIX * WPIX)

__device__ float g_scratch[NBATCH * NSPLIT * IMG];   // 14.7 MB partials (L2-hot)
__device__ int   g_cnt[NBATCH];                      // zero-init; reset by last CTA

__device__ __forceinline__ float ex2f(float a) {
    float r; asm("ex2.approx.f32 %0, %1;" : "=f"(r) : "f"(a)); return r;
}

__global__ __launch_bounds__(BDIM, 3)
void bezier_splat_kernel(const float* __restrict__ x, float* __restrict__ out)
{
    extern __shared__ float acc[];   // [NWARPS][AROWS][STRIDE], per-warp private

    const int task = blockIdx.x;          // 0..1023
    const int b    = task >> 2;
    const int part = task & (NSPLIT - 1);
    const int tid  = threadIdx.x;
    const int w    = tid >> 5;
    const int lane = tid & 31;

    // ---- zero private accumulators ----
    float4* az = (float4*)acc;
    for (int i = tid; i < ACC_WORDS / 4; i += BDIM)
        az[i] = make_float4(0.f, 0.f, 0.f, 0.f);
    __syncthreads();

    float* __restrict__ my = acc + w * COPY_W + RPAD * STRIDE + CPAD;

    const int ra3 = (lane >> 2) + 3;   // row residue (mod 8), pre-biased
    const int pc  = lane & 3;          // column-pair residue (mod 4)

    // ---- per-lane Bezier basis (lane == sample index n), pixel units ----
    const int   n  = (lane < NSAMP) ? lane : (NSAMP - 1);
    const float u  = (float)n * (1.0f / (float)NSAMP);
    const float t  = 2.0f*u*u*u - 3.0f*u*u + 2.0f*u;
    const float t2 = t * t;
    const float t3 = t2 * t;
    const float tb = 1.0f - t;
    const float b0 = 60.0f * t3;
    const float b1 = 180.0f * (t2 - t3);
    const float b2 = 180.0f * (t3 - 2.0f*t2 + t);
    const float b3 = 60.0f * tb * tb * tb;

    const float C2 = -2.0037431123457827f;   // -(5000/3600)*log2(e)
    const float K  = 1.4155363231368842f;    // sqrt(-C2): scaled-coordinate form

    const float* __restrict__ xb = x + ((size_t)b * NCURVE + part * CPT) * 8;

    for (int c = 0; c < CPW; ++c) {
        const float* ct = xb + (w + NWARPS * c) * 8;

        // this lane's sample point on the curve, pixel units, in [0,60)
        const float Xn = b0*ct[0] + b1*ct[2] + b2*ct[4] + b3*ct[6];
        const float Yn = b0*ct[1] + b1*ct[3] + b2*ct[5] + b3*ct[7];

        // ---- compute stage for sample s: (pointer, g1, g2) ----
        float2* pp;   // pending RMW target
        float  pg1, pg2;

        #define COMPUTE(S, PTR, G1, G2)                                          \
        {                                                                        \
            const float Xp = __shfl_sync(0xffffffffu, Xn, (S));                  \
            const float Yp = __shfl_sync(0xffffffffu, Yn, (S));                  \
            const int mi = (int)Xp;            /* [0,59], trunc == floor */      \
            const int mj = (int)Yp;                                              \
            const int i  = mi - 3 + ((ra3 - mi) & 7);                            \
            const int P0 = (mj - 3) >> 1;                                        \
            const int P  = P0 + ((pc - P0) & 3);                                 \
            const float dx  = ((float)i       - Xp) * K;                         \
            const float dy1 = ((float)(2 * P) - Yp) * K;                         \
            const float e1  = fmaf(dy1, -dy1, -(dx * dx));  /* C2*(dx2+dy2) */   \
            const float td  = fmaf(dy1, -2.0f * K, C2);     /* exp delta     */  \
            (G1) = ex2f(e1);                                                     \
            (G2) = ex2f(e1 + td);                                                \
            (PTR) = (float2*)(my + i * STRIDE + 2 * P);                          \
        }

        COMPUTE(0, pp, pg1, pg2)

        #pragma unroll
        for (int s = 1; s < NSAMP; ++s) {
            float2* cp; float cg1, cg2;
            COMPUTE(s, cp, cg1, cg2)          // fills sample s-1's LDS shadow
            float2 v = *pp;                   // RMW for sample s-1
            v.x += pg1; v.y += pg2;
            *pp = v;
            pp = cp; pg1 = cg1; pg2 = cg2;
        }
        {   // drain last sample
            float2 v = *pp;
            v.x += pg1; v.y += pg2;
            *pp = v;
        }
        #undef COMPUTE
    }
    __syncthreads();

    // ---- reduce 4 private copies -> scratch partial (float4) ----
    float4* __restrict__ sp4 = (float4*)(g_scratch + (size_t)task * IMG);
    const float* __restrict__ a0 = acc + RPAD * STRIDE + CPAD;
    for (int q = tid; q < IMG / 4; q += BDIM) {          // 900 quads
        const int i = q / (WPIX / 4);
        const int k = q - i * (WPIX / 4);
        const int o = i * STRIDE + 4 * k;
        float4 s0 = *(const float4*)(a0 + o);
        #pragma unroll
        for (int ww = 1; ww < NWARPS; ++ww) {
            const float4 v = *(const float4*)(a0 + ww * COPY_W + o);
            s0.x += v.x; s0.y += v.y; s0.z += v.z; s0.w += v.w;
        }
        sp4[q] = s0;
    }

    // ---- last task of this batch combines the 4 partials ----
    __threadfence();
    __syncthreads();
    __shared__ int s_last;
    if (tid == 0) {
        int old = atomicAdd(&g_cnt[b], 1);
        s_last = (old == NSPLIT - 1);
    }
    __syncthreads();
    if (s_last) {
        __threadfence();   // acquire: see all tasks' scratch writes
        const float4* __restrict__ base =
            (const float4*)(g_scratch + (size_t)b * NSPLIT * IMG);
        float4* __restrict__ ob = (float4*)(out + (size_t)b * IMG);
        for (int q = tid; q < IMG / 4; q += BDIM) {
            float4 s0 = base[q];
            #pragma unroll
            for (int k = 1; k < NSPLIT; ++k) {
                const float4 v = base[k * (IMG / 4) + q];
                s0.x += v.x; s0.y += v.y; s0.z += v.z; s0.w += v.w;
            }
            s0.x = fminf(s0.x, 1.0f);
            s0.y = fminf(s0.y, 1.0f);
            s0.z = fminf(s0.z, 1.0f);
            s0.w = fminf(s0.w, 1.0f);
            ob[q] = s0;
        }
        if (tid == 0) g_cnt[b] = 0;   // reset for next graph replay
    }
}

extern "C" void kernel_launch(void* const* d_in, const int* in_sizes, int n_in,
                              void* d_out, int out_size)
{
    (void)in_sizes; (void)n_in; (void)out_size;
    const float* x = (const float*)d_in[0];
    float* out     = (float*)d_out;

    cudaFuncSetAttribute(bezier_splat_kernel,
                         cudaFuncAttributeMaxDynamicSharedMemorySize,
                         ACC_WORDS * (int)sizeof(float));

    bezier_splat_kernel<<<NBATCH * NSPLIT, BDIM, ACC_WORDS * (int)sizeof(float)>>>(x, out);
}

// round 10
// speedup vs baseline: 1.2576x; 1.1888x over previous
#include <cuda_runtime.h>

// BezierToImageLayer — sparse Gaussian splat, round 10.
// R10 = R9 (two curves per warp) with the inter-half race FIXED:
//  - each lane commits its two cells in residue-phased order:
//    half0: pair-residues {0,1} then {2,3};  half1: {2,3} then {0,1}
//    (off1 = ((q-P0)&3) ^ (half<<1); off2 = off1^2 — zero extra instructions).
//    Within a phase the halves touch provably different cells; across phases
//    same-warp program order serializes any collision.
//  - compiler fence between the two RMWs: off2 = off1^2 is provably != off1,
//    so without the fence alias analysis may hoist LDS2 above STS1 (unsound here).
//  - everything else (NSPLIT=4, epilogue, fused combine) identical to R6/R8.

#define BDIM     128
#define NWARPS   4
#define NSPLIT   4
#define WPIX     60
#define AROWS    67                         // rows -3..63
#define STRIDE   68                         // bank-pair (2i+P) mod 16: 2-phase LDS.64
#define RPAD     3
#define CPAD     4
#define NSAMP    30
#define NCURVE   160
#define CPT      (NCURVE / NSPLIT)          // 40 curves per task
#define PAIRS_W  (CPT / NWARPS / 2)         // 5 curve-pairs per warp
#define COPY_W   (AROWS * STRIDE)           // 4556 floats
#define ACC_WORDS (NWARPS * COPY_W)         // 18224 floats = 72896 B

#define NBATCH   256
#define IMG      (WPIX * WPIX)

__device__ float g_scratch[NBATCH * NSPLIT * IMG];   // 14.7 MB partials (L2-hot)
__device__ int   g_cnt[NBATCH];                      // zero-init; reset by last CTA

__device__ __forceinline__ float ex2f(float a) {
    float r; asm("ex2.approx.f32 %0, %1;" : "=f"(r) : "f"(a)); return r;
}

__global__ __launch_bounds__(BDIM, 3)
void bezier_splat_kernel(const float* __restrict__ x, float* __restrict__ out)
{
    extern __shared__ float acc[];   // [NWARPS][AROWS][STRIDE], per-warp private

    const int task = blockIdx.x;          // 0..1023
    const int b    = task >> 2;
    const int part = task & (NSPLIT - 1);
    const int tid  = threadIdx.x;
    const int w    = tid >> 5;
    const int lane = tid & 31;

    // ---- zero private accumulators ----
    float4* az = (float4*)acc;
    for (int i = tid; i < ACC_WORDS / 4; i += BDIM)
        az[i] = make_float4(0.f, 0.f, 0.f, 0.f);
    __syncthreads();

    float* __restrict__ my = acc + w * COPY_W + RPAD * STRIDE + CPAD;

    const int half = lane >> 4;        // which curve of the pair
    const int hb   = half << 1;        // phase-order swap for half 1
    const int hl   = lane & 15;
    const int q    = hl & 1;           // base col-pair residue (mod 4)
    const int rl3  = (hl >> 1) + 3;    // row residue (mod 8), pre-biased

    // ---- basis for this lane's two sample indices: n_lo = hl, n_hi = hl+16 ----
    float bl[4], bh[4];
    #pragma unroll
    for (int k = 0; k < 2; ++k) {
        int nn = hl + 16 * k;  if (nn >= NSAMP) nn = NSAMP - 1;
        const float u  = (float)nn * (1.0f / (float)NSAMP);
        const float t  = 2.0f*u*u*u - 3.0f*u*u + 2.0f*u;
        const float t2 = t * t;
        const float t3 = t2 * t;
        const float tb = 1.0f - t;
        float* bb = k ? bh : bl;
        bb[0] = 60.0f  * t3;
        bb[1] = 180.0f * (t2 - t3);
        bb[2] = 180.0f * (t3 - 2.0f*t2 + t);
        bb[3] = 60.0f  * tb * tb * tb;
    }

    const float C2 = -2.0037431123457827f;   // -(5000/3600)*log2(e)
    const float K  = 1.4155363231368842f;    // sqrt(-C2)

    const float* __restrict__ xb = x + ((size_t)b * NCURVE + part * CPT) * 8;

    for (int cp = 0; cp < PAIRS_W; ++cp) {
        const int pi = w + NWARPS * cp;               // pair index 0..19
        const float* ct = xb + (2 * pi + half) * 8;   // uniform per half-warp

        // this lane's two sample points (pixel units, [0,60))
        const float Xlo = bl[0]*ct[0] + bl[1]*ct[2] + bl[2]*ct[4] + bl[3]*ct[6];
        const float Ylo = bl[0]*ct[1] + bl[1]*ct[3] + bl[2]*ct[5] + bl[3]*ct[7];
        const float Xhi = bh[0]*ct[0] + bh[1]*ct[2] + bh[2]*ct[4] + bh[3]*ct[6];
        const float Yhi = bh[0]*ct[1] + bh[1]*ct[3] + bh[2]*ct[5] + bh[3]*ct[7];

        #pragma unroll
        for (int s = 0; s < NSAMP; ++s) {
            // half-warp broadcast (width 16): each half gets ITS curve's sample s
            const float Xp = (s < 16) ? __shfl_sync(0xffffffffu, Xlo, s, 16)
                                      : __shfl_sync(0xffffffffu, Xhi, s - 16, 16);
            const float Yp = (s < 16) ? __shfl_sync(0xffffffffu, Ylo, s, 16)
                                      : __shfl_sync(0xffffffffu, Yhi, s - 16, 16);

            const int mi = (int)Xp;                  // [0,59], trunc == floor
            const int mj = (int)Yp;

            const int i   = mi - 3 + ((rl3 - mi) & 7);   // row, ≡ rl (mod 8)
            const int P0  = (mj - 3) >> 1;
            const int off1 = (((q - P0) & 3) ^ hb);       // phase-1 residue set
            const int off2 = off1 ^ 2;                    // phase-2 residue set
            const int P1  = P0 + off1;
            const int P2  = P0 + off2;

            const float dx  = ((float)i        - Xp) * K;
            const float dy1 = ((float)(2 * P1) - Yp) * K;
            const float dy2 = ((float)(2 * P2) - Yp) * K;

            const float nx  = -(dx * dx);
            const float e1  = fmaf(dy1, -dy1, nx);
            const float e2  = fmaf(dy2, -dy2, nx);
            const float td1 = fmaf(dy1, -2.0f * K, C2);
            const float td2 = fmaf(dy2, -2.0f * K, C2);

            const float g11 = ex2f(e1);
            const float g12 = ex2f(e1 + td1);
            const float g21 = ex2f(e2);
            const float g22 = ex2f(e2 + td2);

            float* __restrict__ row = my + i * STRIDE;

            // phase 1: halves touch disjoint pair-residues -> no intra-instr collision
            {
                float2* p1 = (float2*)(row + 2 * P1);
                float2 v = *p1;
                v.x += g11; v.y += g12;
                *p1 = v;
            }
            // fence: off2 = off1^2 is provably != off1; stop LDS2 hoisting above STS1
            asm volatile("" ::: "memory");
            // phase 2: swapped residue sets; cross-phase collisions ordered by program order
            {
                float2* p2 = (float2*)(row + 2 * P2);
                float2 v = *p2;
                v.x += g21; v.y += g22;
                *p2 = v;
            }
        }
    }
    __syncthreads();

    // ---- reduce 4 private copies -> scratch partial (float4) ----
    float4* __restrict__ sp4 = (float4*)(g_scratch + (size_t)task * IMG);
    const float* __restrict__ a0 = acc + RPAD * STRIDE + CPAD;
    for (int qd = tid; qd < IMG / 4; qd += BDIM) {        // 900 quads
        const int i = qd / (WPIX / 4);
        const int k = qd - i * (WPIX / 4);
        const int o = i * STRIDE + 4 * k;
        float4 s0 = *(const float4*)(a0 + o);
        #pragma unroll
        for (int ww = 1; ww < NWARPS; ++ww) {
            const float4 v = *(const float4*)(a0 + ww * COPY_W + o);
            s0.x += v.x; s0.y += v.y; s0.z += v.z; s0.w += v.w;
        }
        sp4[qd] = s0;
    }

    // ---- last task of this batch combines the 4 partials ----
    __threadfence();
    __syncthreads();
    __shared__ int s_last;
    if (tid == 0) {
        int old = atomicAdd(&g_cnt[b], 1);
        s_last = (old == NSPLIT - 1);
    }
    __syncthreads();
    if (s_last) {
        __threadfence();   // acquire: see all tasks' scratch writes
        const float4* __restrict__ base =
            (const float4*)(g_scratch + (size_t)b * NSPLIT * IMG);
        float4* __restrict__ ob = (float4*)(out + (size_t)b * IMG);
        for (int qd = tid; qd < IMG / 4; qd += BDIM) {
            float4 s0 = base[qd];
            #pragma unroll
            for (int k = 1; k < NSPLIT; ++k) {
                const float4 v = base[k * (IMG / 4) + qd];
                s0.x += v.x; s0.y += v.y; s0.z += v.z; s0.w += v.w;
            }
            s0.x = fminf(s0.x, 1.0f);
            s0.y = fminf(s0.y, 1.0f);
            s0.z = fminf(s0.z, 1.0f);
            s0.w = fminf(s0.w, 1.0f);
            ob[qd] = s0;
        }
        if (tid == 0) g_cnt[b] = 0;   // reset for next graph replay
    }
}

extern "C" void kernel_launch(void* const* d_in, const int* in_sizes, int n_in,
                              void* d_out, int out_size)
{
    (void)in_sizes; (void)n_in; (void)out_size;
    const float* x = (const float*)d_in[0];
    float* out     = (float*)d_out;

    cudaFuncSetAttribute(bezier_splat_kernel,
                         cudaFuncAttributeMaxDynamicSharedMemorySize,
                         ACC_WORDS * (int)sizeof(float));

    bezier_splat_kernel<<<NBATCH * NSPLIT, BDIM, ACC_WORDS * (int)sizeof(float)>>>(x, out);
}